// round 8
// baseline (speedup 1.0000x reference)
#include <cuda_runtime.h>
#include <cuda_bf16.h>
#include <cuda_fp16.h>
#include <cstdint>

#define N_NODES 100000
#define IN_F    512
#define HID     128
#define NCLS    2
#define MAX_E   1600000
#define SCAN_BLK 1024
#define NUM_SCAN_BLKS ((N_NODES + SCAN_BLK - 1) / SCAN_BLK)   // 98

// ---------------- device scratch (static globals; no runtime allocation) ----
__device__ __half g_xw [(size_t)N_NODES * HID];   // fp16: norm_src * (X@W1)
__device__ float  g_zs [(size_t)N_NODES * NCLS];  // norm_src * (h@W2)
__device__ float  g_norm_src[N_NODES];
__device__ float  g_norm_dst[N_NODES];
__device__ int    g_src32[MAX_E];
__device__ int    g_dst32[MAX_E];
__device__ int    g_csr_src[MAX_E];
__device__ int    g_in_cnt[N_NODES];
__device__ int    g_out_cnt[N_NODES];
__device__ int    g_row_start[N_NODES];
__device__ int    g_cursor[N_NODES];
__device__ int    g_blk_sums[NUM_SCAN_BLKS];
__device__ int    g_blk_off[NUM_SCAN_BLKS];
__device__ int    g_is64;
// W1 transposed + bf16 hi/lo split: [HID n][IN_F k] as bf16 pairs (uint32)
__device__ uint32_t g_w1t_hi[(HID * IN_F) / 2];
__device__ uint32_t g_w1t_lo[(HID * IN_F) / 2];

// ---------------- zero the histograms ---------------------------------------
__global__ void zero_kernel() {
    int i = blockIdx.x * blockDim.x + threadIdx.x;
    if (i < N_NODES) {
        g_in_cnt[i] = 0;
        g_out_cnt[i] = 0;
    }
}

// ---------------- index dtype detection -------------------------------------
__global__ void detect_kernel(const void* src_raw, int E) {
    const unsigned int* p = (const unsigned int*)src_raw;
    int n = E < 64 ? E : 64;
    int is64 = 1;
    for (int i = 0; i < n; i++)
        if (p[2 * i + 1] != 0u) is64 = 0;
    g_is64 = is64;
}

// ---------------- convert + degree histograms -------------------------------
__global__ void convert_degree_kernel(const void* src_raw, const void* dst_raw, int E) {
    int i = blockIdx.x * blockDim.x + threadIdx.x;
    if (i >= E) return;
    int s, d;
    if (g_is64) {
        s = (int)((const long long*)src_raw)[i];
        d = (int)((const long long*)dst_raw)[i];
    } else {
        s = ((const int*)src_raw)[i];
        d = ((const int*)dst_raw)[i];
    }
    g_src32[i] = s;
    g_dst32[i] = d;
    atomicAdd(&g_out_cnt[s], 1);
    atomicAdd(&g_in_cnt[d], 1);
}

// ---------------- prefix scan over in_cnt (3 phases) -------------------------
__global__ void __launch_bounds__(SCAN_BLK) scanA_kernel() {
    __shared__ int sh[SCAN_BLK];
    int tid = threadIdx.x;
    int i = blockIdx.x * SCAN_BLK + tid;
    int v = (i < N_NODES) ? g_in_cnt[i] : 0;
    sh[tid] = v;
    __syncthreads();
#pragma unroll
    for (int off = 1; off < SCAN_BLK; off <<= 1) {
        int t = (tid >= off) ? sh[tid - off] : 0;
        __syncthreads();
        sh[tid] += t;
        __syncthreads();
    }
    if (i < N_NODES) g_row_start[i] = sh[tid];
    if (tid == SCAN_BLK - 1) g_blk_sums[blockIdx.x] = sh[tid];
}

__global__ void scanB_kernel() {
    __shared__ int sh[128];
    int tid = threadIdx.x;
    int v = (tid < NUM_SCAN_BLKS) ? g_blk_sums[tid] : 0;
    sh[tid] = v;
    __syncthreads();
#pragma unroll
    for (int off = 1; off < 128; off <<= 1) {
        int t = (tid >= off) ? sh[tid - off] : 0;
        __syncthreads();
        sh[tid] += t;
        __syncthreads();
    }
    if (tid < NUM_SCAN_BLKS) g_blk_off[tid] = sh[tid] - v;
}

__global__ void scanC_kernel() {
    int i = blockIdx.x * blockDim.x + threadIdx.x;
    if (i >= N_NODES) return;
    int ic = g_in_cnt[i];
    int excl = g_row_start[i] - ic + g_blk_off[i >> 10];
    g_row_start[i] = excl;
    g_cursor[i] = excl;
    g_norm_src[i] = rsqrtf(fmaxf((float)g_out_cnt[i], 1.0f));
    g_norm_dst[i] = rsqrtf(fmaxf((float)ic, 1.0f));
}

// ---------------- scatter edges into CSR (grouped by dst) --------------------
__global__ void scatter_kernel(int E) {
    int e = blockIdx.x * blockDim.x + threadIdx.x;
    if (e >= E) return;
    int d = g_dst32[e];
    int pos = atomicAdd(&g_cursor[d], 1);
    g_csr_src[pos] = g_src32[e];
}

// ---------------- W1 transpose + bf16 hi/lo split ----------------------------
// Output layout: bf16 at [n][k] => uint32 pair index n*(IN_F/2) + k/2.
__global__ void w1prep_kernel(const float* __restrict__ W1) {
    int i = blockIdx.x * blockDim.x + threadIdx.x;   // over (IN_F/2)*HID pairs
    if (i >= (IN_F / 2) * HID) return;
    int n  = i >> 8;            // 0..127  (IN_F/2 = 256 pairs per n)
    int kp = i & 255;           // pair index
    float v0 = W1[(size_t)(2 * kp + 0) * HID + n];
    float v1 = W1[(size_t)(2 * kp + 1) * HID + n];
    __nv_bfloat16 h0 = __float2bfloat16(v0);
    __nv_bfloat16 h1 = __float2bfloat16(v1);
    float l0 = v0 - __bfloat162float(h0);
    float l1 = v1 - __bfloat162float(h1);
    __nv_bfloat162 ph = __halves2bfloat162(h0, h1);
    __nv_bfloat162 pl = __halves2bfloat162(__float2bfloat16(l0), __float2bfloat16(l1));
    g_w1t_hi[(size_t)n * (IN_F / 2) + kp] = *reinterpret_cast<uint32_t*>(&ph);
    g_w1t_lo[(size_t)n * (IN_F / 2) + kp] = *reinterpret_cast<uint32_t*>(&pl);
}

// ---------------- GEMM1 (mma.sync tensor cores, bf16 2-term split) ----------
__device__ __forceinline__ void mma_bf16(float* c, const uint32_t* a, const uint32_t* b) {
    asm volatile(
        "mma.sync.aligned.m16n8k16.row.col.f32.bf16.bf16.f32 "
        "{%0,%1,%2,%3}, {%4,%5,%6,%7}, {%8,%9}, {%0,%1,%2,%3};\n"
        : "+f"(c[0]), "+f"(c[1]), "+f"(c[2]), "+f"(c[3])
        : "r"(a[0]), "r"(a[1]), "r"(a[2]), "r"(a[3]), "r"(b[0]), "r"(b[1]));
}

__device__ __forceinline__ uint32_t pack_bf16_hi(float x, float y,
                                                 float& lox, float& loy) {
    __nv_bfloat16 hx = __float2bfloat16(x);
    __nv_bfloat16 hy = __float2bfloat16(y);
    lox = x - __bfloat162float(hx);
    loy = y - __bfloat162float(hy);
    __nv_bfloat162 p = __halves2bfloat162(hx, hy);
    return *reinterpret_cast<uint32_t*>(&p);
}

__device__ __forceinline__ uint32_t pack_bf16(float x, float y) {
    __nv_bfloat162 p = __halves2bfloat162(__float2bfloat16(x), __float2bfloat16(y));
    return *reinterpret_cast<uint32_t*>(&p);
}

__global__ void __launch_bounds__(512, 1) gemm1_tc_kernel(const float* __restrict__ X) {
    __shared__ uint32_t As_hi[128][9];
    __shared__ uint32_t As_lo[128][9];
    __shared__ uint32_t Bs_hi[128][9];
    __shared__ uint32_t Bs_lo[128][9];

    const int tid = threadIdx.x;
    const int warp = tid >> 5;
    const int lane = tid & 31;
    const int g  = lane >> 2;
    const int tg = lane & 3;
    const int wm = warp >> 2;
    const int wn = warp & 3;
    const int block_row = blockIdx.x * 128;

    int a_row[2], a_kp[2], b_n[2], b_kp[2];
#pragma unroll
    for (int it = 0; it < 2; it++) {
        int idx = tid + it * 512;
        a_row[it] = idx >> 3;
        a_kp[it]  = idx & 7;
        // COALESCED mapping for [n][k] layout: consecutive threads walk k-pairs
        b_n[it]   = idx >> 3;       // 0..127
        b_kp[it]  = idx & 7;        // 0..7
    }

    float acc[2][4][4];
#pragma unroll
    for (int mt = 0; mt < 2; mt++)
#pragma unroll
        for (int nt = 0; nt < 4; nt++)
#pragma unroll
            for (int r = 0; r < 4; r++) acc[mt][nt][r] = 0.f;

    float2   pa[2];
    uint32_t pbh[2], pbl[2];

    auto load_tile = [&](int kk) {
#pragma unroll
        for (int it = 0; it < 2; it++) {
            int gr = block_row + a_row[it];
            float2 v = make_float2(0.f, 0.f);
            if (gr < N_NODES)
                v = *(const float2*)(X + (size_t)gr * IN_F + kk + a_kp[it] * 2);
            pa[it] = v;
            int bidx = b_n[it] * (IN_F / 2) + (kk >> 1) + b_kp[it];
            pbh[it] = g_w1t_hi[bidx];
            pbl[it] = g_w1t_lo[bidx];
        }
    };

    auto store_tile = [&]() {
#pragma unroll
        for (int it = 0; it < 2; it++) {
            float lx, ly;
            As_hi[a_row[it]][a_kp[it]] = pack_bf16_hi(pa[it].x, pa[it].y, lx, ly);
            As_lo[a_row[it]][a_kp[it]] = pack_bf16(lx, ly);
            Bs_hi[b_n[it]][b_kp[it]] = pbh[it];
            Bs_lo[b_n[it]][b_kp[it]] = pbl[it];
        }
    };

    load_tile(0);

    for (int kk = 0; kk < IN_F; kk += 16) {
        store_tile();
        __syncthreads();

        if (kk + 16 < IN_F) load_tile(kk + 16);

        uint32_t Ahi[2][4], Alo[2][4], Bhi[4][2], Blo[4][2];
#pragma unroll
        for (int mt = 0; mt < 2; mt++) {
            int r0 = wm * 32 + mt * 16 + g;
            int r1 = r0 + 8;
            Ahi[mt][0] = As_hi[r0][tg];     Ahi[mt][1] = As_hi[r1][tg];
            Ahi[mt][2] = As_hi[r0][tg + 4]; Ahi[mt][3] = As_hi[r1][tg + 4];
            Alo[mt][0] = As_lo[r0][tg];     Alo[mt][1] = As_lo[r1][tg];
            Alo[mt][2] = As_lo[r0][tg + 4]; Alo[mt][3] = As_lo[r1][tg + 4];
        }
#pragma unroll
        for (int nt = 0; nt < 4; nt++) {
            int c = wn * 32 + nt * 8 + g;
            Bhi[nt][0] = Bs_hi[c][tg]; Bhi[nt][1] = Bs_hi[c][tg + 4];
            Blo[nt][0] = Bs_lo[c][tg]; Blo[nt][1] = Bs_lo[c][tg + 4];
        }

#pragma unroll
        for (int mt = 0; mt < 2; mt++)
#pragma unroll
            for (int nt = 0; nt < 4; nt++) {
                mma_bf16(acc[mt][nt], Ahi[mt], Bhi[nt]);
                mma_bf16(acc[mt][nt], Alo[mt], Bhi[nt]);
                mma_bf16(acc[mt][nt], Ahi[mt], Blo[nt]);
            }
        __syncthreads();
    }

    // epilogue: scale by norm_src, convert to fp16, store
#pragma unroll
    for (int mt = 0; mt < 2; mt++) {
        int row0 = block_row + wm * 32 + mt * 16 + g;
        int row1 = row0 + 8;
        float ns0 = (row0 < N_NODES) ? g_norm_src[row0] : 0.f;
        float ns1 = (row1 < N_NODES) ? g_norm_src[row1] : 0.f;
#pragma unroll
        for (int nt = 0; nt < 4; nt++) {
            int col = wn * 32 + nt * 8 + 2 * tg;
            if (row0 < N_NODES) {
                __half2 v = __floats2half2_rn(acc[mt][nt][0] * ns0, acc[mt][nt][1] * ns0);
                *(__half2*)&g_xw[(size_t)row0 * HID + col] = v;
            }
            if (row1 < N_NODES) {
                __half2 v = __floats2half2_rn(acc[mt][nt][2] * ns1, acc[mt][nt][3] * ns1);
                *(__half2*)&g_xw[(size_t)row1 * HID + col] = v;
            }
        }
    }
}

// ---------------- fused layer1: CSR segmented sum + relu + lin2 --------------
// warp per dst node; fp16 gather (8B per lane per message), fp32 accum.
__global__ void __launch_bounds__(256) agg1_fused_kernel(const float* __restrict__ b1,
                                                         const float* __restrict__ W2) {
    __shared__ float sW2[HID * 2];
    __shared__ float sb1[HID];
    for (int i = threadIdx.x; i < HID * 2; i += 256) sW2[i] = W2[i];
    for (int i = threadIdx.x; i < HID; i += 256) sb1[i] = b1[i];
    __syncthreads();

    int gid = blockIdx.x * blockDim.x + threadIdx.x;
    int row = gid >> 5;
    if (row >= N_NODES) return;
    int lane = gid & 31;

    int start = g_row_start[row];
    int cnt   = g_in_cnt[row];
    int end   = start + cnt;

    const __half* xw = g_xw;
    float4 acc = make_float4(0.f, 0.f, 0.f, 0.f);
    int e = start;
    for (; e + 3 < end; e += 4) {
        int s0 = __ldg(&g_csr_src[e + 0]);
        int s1 = __ldg(&g_csr_src[e + 1]);
        int s2 = __ldg(&g_csr_src[e + 2]);
        int s3 = __ldg(&g_csr_src[e + 3]);
        uint2 u0 = *(const uint2*)&xw[(size_t)s0 * HID + lane * 4];
        uint2 u1 = *(const uint2*)&xw[(size_t)s1 * HID + lane * 4];
        uint2 u2 = *(const uint2*)&xw[(size_t)s2 * HID + lane * 4];
        uint2 u3 = *(const uint2*)&xw[(size_t)s3 * HID + lane * 4];
        float2 a0 = __half22float2(*(__half2*)&u0.x), b0 = __half22float2(*(__half2*)&u0.y);
        float2 a1 = __half22float2(*(__half2*)&u1.x), b1v = __half22float2(*(__half2*)&u1.y);
        float2 a2 = __half22float2(*(__half2*)&u2.x), b2v = __half22float2(*(__half2*)&u2.y);
        float2 a3 = __half22float2(*(__half2*)&u3.x), b3v = __half22float2(*(__half2*)&u3.y);
        acc.x += (a0.x + a1.x) + (a2.x + a3.x);
        acc.y += (a0.y + a1.y) + (a2.y + a3.y);
        acc.z += (b0.x + b1v.x) + (b2v.x + b3v.x);
        acc.w += (b0.y + b1v.y) + (b2v.y + b3v.y);
    }
    for (; e < end; e++) {
        int s0 = __ldg(&g_csr_src[e]);
        uint2 u0 = *(const uint2*)&xw[(size_t)s0 * HID + lane * 4];
        float2 a0 = __half22float2(*(__half2*)&u0.x), b0 = __half22float2(*(__half2*)&u0.y);
        acc.x += a0.x; acc.y += a0.y; acc.z += b0.x; acc.w += b0.y;
    }

    float nd = g_norm_dst[row];
    int k0 = lane * 4;
    float h0 = fmaxf(acc.x * nd + sb1[k0 + 0], 0.f);
    float h1 = fmaxf(acc.y * nd + sb1[k0 + 1], 0.f);
    float h2 = fmaxf(acc.z * nd + sb1[k0 + 2], 0.f);
    float h3 = fmaxf(acc.w * nd + sb1[k0 + 3], 0.f);

    float s0 = h0 * sW2[(k0 + 0) * 2] + h1 * sW2[(k0 + 1) * 2]
             + h2 * sW2[(k0 + 2) * 2] + h3 * sW2[(k0 + 3) * 2];
    float s1 = h0 * sW2[(k0 + 0) * 2 + 1] + h1 * sW2[(k0 + 1) * 2 + 1]
             + h2 * sW2[(k0 + 2) * 2 + 1] + h3 * sW2[(k0 + 3) * 2 + 1];
#pragma unroll
    for (int off = 16; off > 0; off >>= 1) {
        s0 += __shfl_down_sync(0xffffffffu, s0, off);
        s1 += __shfl_down_sync(0xffffffffu, s1, off);
    }
    if (lane == 0) {
        float ns = g_norm_src[row];
        g_zs[row * 2 + 0] = s0 * ns;
        g_zs[row * 2 + 1] = s1 * ns;
    }
}

// ---------------- fused layer2: CSR segmented sum + softmax ------------------
__global__ void agg2_fused_kernel(const float* __restrict__ b2, float* __restrict__ out) {
    int i = blockIdx.x * blockDim.x + threadIdx.x;
    if (i >= N_NODES) return;
    int start = g_row_start[i];
    int end = start + g_in_cnt[i];
    float a0 = 0.f, a1 = 0.f;
    int e = start;
    for (; e + 1 < end; e += 2) {
        int s0 = __ldg(&g_csr_src[e]);
        int s1 = __ldg(&g_csr_src[e + 1]);
        float2 v0 = *(const float2*)&g_zs[s0 * 2];
        float2 v1 = *(const float2*)&g_zs[s1 * 2];
        a0 += v0.x + v1.x;
        a1 += v0.y + v1.y;
    }
    if (e < end) {
        int s = __ldg(&g_csr_src[e]);
        float2 v = *(const float2*)&g_zs[s * 2];
        a0 += v.x;
        a1 += v.y;
    }
    float nd = g_norm_dst[i];
    float z0 = a0 * nd + __ldg(&b2[0]);
    float z1 = a1 * nd + __ldg(&b2[1]);
    float m = fmaxf(z0, z1);
    float e0 = __expf(z0 - m);
    float e1 = __expf(z1 - m);
    float inv = 1.0f / (e0 + e1);
    out[i * 2 + 0] = e0 * inv;
    out[i * 2 + 1] = e1 * inv;
}

// ---------------- host ------------------------------------------------------
extern "C" void kernel_launch(void* const* d_in, const int* in_sizes, int n_in,
                              void* d_out, int out_size) {
    const float* X  = (const float*)d_in[0];
    const float* W1 = (const float*)d_in[1];
    const float* b1 = (const float*)d_in[2];
    const float* W2 = (const float*)d_in[3];
    const float* b2 = (const float*)d_in[4];
    const void*  sp = d_in[5];
    const void*  dp = d_in[6];
    const int E = in_sizes[5];
    float* out = (float*)d_out;

    zero_kernel<<<(N_NODES + 255) / 256, 256>>>();
    detect_kernel<<<1, 1>>>(sp, E);
    convert_degree_kernel<<<(E + 255) / 256, 256>>>(sp, dp, E);
    scanA_kernel<<<NUM_SCAN_BLKS, SCAN_BLK>>>();
    scanB_kernel<<<1, 128>>>();
    scanC_kernel<<<(N_NODES + 255) / 256, 256>>>();
    scatter_kernel<<<(E + 255) / 256, 256>>>(E);
    w1prep_kernel<<<((IN_F / 2) * HID + 255) / 256, 256>>>(W1);
    gemm1_tc_kernel<<<(N_NODES + 127) / 128, 512>>>(X);
    {
        long long threads = (long long)N_NODES * 32;
        agg1_fused_kernel<<<(unsigned)((threads + 255) / 256), 256>>>(b1, W2);
    }
    agg2_fused_kernel<<<(N_NODES + 255) / 256, 256>>>(b2, out);
}

// round 10
// speedup vs baseline: 1.4563x; 1.4563x over previous
#include <cuda_runtime.h>
#include <cuda_bf16.h>
#include <cuda_fp16.h>
#include <cstdint>

#define N_NODES 100000
#define IN_F    512
#define HID     128
#define NCLS    2
#define MAX_E   1600000
#define SCAN_BLK 1024
#define NUM_SCAN_BLKS ((N_NODES + SCAN_BLK - 1) / SCAN_BLK)   // 98

// ---------------- device scratch (static globals; no runtime allocation) ----
__device__ __half g_xw [(size_t)N_NODES * HID];   // fp16: norm_src * (X@W1)
__device__ float  g_zs [(size_t)N_NODES * NCLS];  // norm_src * (h@W2)
__device__ float  g_norm_src[N_NODES];
__device__ float  g_norm_dst[N_NODES];
__device__ int    g_src32[MAX_E];
__device__ int    g_dst32[MAX_E];
__device__ int    g_csr_src[MAX_E];
__device__ int    g_in_cnt[N_NODES];
__device__ int    g_out_cnt[N_NODES];
__device__ int    g_row_start[N_NODES];
__device__ int    g_cursor[N_NODES];
__device__ int    g_blk_sums[NUM_SCAN_BLKS];
__device__ int    g_blk_off[NUM_SCAN_BLKS];
__device__ int    g_is64;

// ---------------- zero histograms + index dtype detection (fused) -----------
__global__ void zerodetect_kernel(const void* src_raw, int E) {
    int i = blockIdx.x * blockDim.x + threadIdx.x;
    if (i < N_NODES) {
        g_in_cnt[i] = 0;
        g_out_cnt[i] = 0;
    }
    if (blockIdx.x == 0 && threadIdx.x == 0) {
        const unsigned int* p = (const unsigned int*)src_raw;
        int n = E < 64 ? E : 64;
        int is64 = 1;
        for (int j = 0; j < n; j++)
            if (p[2 * j + 1] != 0u) is64 = 0;
        g_is64 = is64;
    }
}

// ---------------- convert + degree histograms -------------------------------
__global__ void convert_degree_kernel(const void* src_raw, const void* dst_raw, int E) {
    int i = blockIdx.x * blockDim.x + threadIdx.x;
    if (i >= E) return;
    int s, d;
    if (g_is64) {
        s = (int)((const long long*)src_raw)[i];
        d = (int)((const long long*)dst_raw)[i];
    } else {
        s = ((const int*)src_raw)[i];
        d = ((const int*)dst_raw)[i];
    }
    g_src32[i] = s;
    g_dst32[i] = d;
    atomicAdd(&g_out_cnt[s], 1);
    atomicAdd(&g_in_cnt[d], 1);
}

// ---------------- norms (before GEMM so epilogue can scale) ------------------
__global__ void norm_kernel() {
    int i = blockIdx.x * blockDim.x + threadIdx.x;
    if (i >= N_NODES) return;
    g_norm_src[i] = rsqrtf(fmaxf((float)g_out_cnt[i], 1.0f));
    g_norm_dst[i] = rsqrtf(fmaxf((float)g_in_cnt[i], 1.0f));
}

// ---------------- GEMM1 (round-4 form; fp16 output) -------------------------
__device__ __forceinline__ void mma_bf16(float* c, const uint32_t* a, const uint32_t* b) {
    asm volatile(
        "mma.sync.aligned.m16n8k16.row.col.f32.bf16.bf16.f32 "
        "{%0,%1,%2,%3}, {%4,%5,%6,%7}, {%8,%9}, {%0,%1,%2,%3};\n"
        : "+f"(c[0]), "+f"(c[1]), "+f"(c[2]), "+f"(c[3])
        : "r"(a[0]), "r"(a[1]), "r"(a[2]), "r"(a[3]), "r"(b[0]), "r"(b[1]));
}

__device__ __forceinline__ uint32_t pack_bf16_hi(float x, float y,
                                                 float& lox, float& loy) {
    __nv_bfloat16 hx = __float2bfloat16(x);
    __nv_bfloat16 hy = __float2bfloat16(y);
    lox = x - __bfloat162float(hx);
    loy = y - __bfloat162float(hy);
    __nv_bfloat162 p = __halves2bfloat162(hx, hy);
    return *reinterpret_cast<uint32_t*>(&p);
}

__device__ __forceinline__ uint32_t pack_bf16(float x, float y) {
    __nv_bfloat162 p = __halves2bfloat162(__float2bfloat16(x), __float2bfloat16(y));
    return *reinterpret_cast<uint32_t*>(&p);
}

__global__ void __launch_bounds__(512, 1) gemm1_tc_kernel(const float* __restrict__ X,
                                                          const float* __restrict__ W1) {
    __shared__ uint32_t As_hi[128][9];
    __shared__ uint32_t As_lo[128][9];
    __shared__ uint32_t Bs_hi[128][9];
    __shared__ uint32_t Bs_lo[128][9];

    const int tid = threadIdx.x;
    const int warp = tid >> 5;
    const int lane = tid & 31;
    const int g  = lane >> 2;
    const int tg = lane & 3;
    const int wm = warp >> 2;
    const int wn = warp & 3;
    const int block_row = blockIdx.x * 128;

    int a_row[2], a_kp[2], b_n[2], b_kp[2];
#pragma unroll
    for (int it = 0; it < 2; it++) {
        int idx = tid + it * 512;
        a_row[it] = idx >> 3;
        a_kp[it]  = idx & 7;
        b_n[it]   = idx & 127;     // round-4 mapping: [k][n] fp32 W1, coalesced over n
        b_kp[it]  = idx >> 7;
    }

    float acc[2][4][4];
#pragma unroll
    for (int mt = 0; mt < 2; mt++)
#pragma unroll
        for (int nt = 0; nt < 4; nt++)
#pragma unroll
            for (int r = 0; r < 4; r++) acc[mt][nt][r] = 0.f;

    float2 pa[2];
    float  pb0[2], pb1[2];

    auto load_tile = [&](int kk) {
#pragma unroll
        for (int it = 0; it < 2; it++) {
            int gr = block_row + a_row[it];
            float2 v = make_float2(0.f, 0.f);
            if (gr < N_NODES)
                v = *(const float2*)(X + (size_t)gr * IN_F + kk + a_kp[it] * 2);
            pa[it] = v;
            pb0[it] = W1[(size_t)(kk + 2 * b_kp[it]) * HID + b_n[it]];
            pb1[it] = W1[(size_t)(kk + 2 * b_kp[it] + 1) * HID + b_n[it]];
        }
    };

    auto store_tile = [&]() {
#pragma unroll
        for (int it = 0; it < 2; it++) {
            float lx, ly;
            As_hi[a_row[it]][a_kp[it]] = pack_bf16_hi(pa[it].x, pa[it].y, lx, ly);
            As_lo[a_row[it]][a_kp[it]] = pack_bf16(lx, ly);
            float blx, bly;
            Bs_hi[b_n[it]][b_kp[it]] = pack_bf16_hi(pb0[it], pb1[it], blx, bly);
            Bs_lo[b_n[it]][b_kp[it]] = pack_bf16(blx, bly);
        }
    };

    load_tile(0);

    for (int kk = 0; kk < IN_F; kk += 16) {
        store_tile();
        __syncthreads();

        if (kk + 16 < IN_F) load_tile(kk + 16);

        uint32_t Ahi[2][4], Alo[2][4], Bhi[4][2], Blo[4][2];
#pragma unroll
        for (int mt = 0; mt < 2; mt++) {
            int r0 = wm * 32 + mt * 16 + g;
            int r1 = r0 + 8;
            Ahi[mt][0] = As_hi[r0][tg];     Ahi[mt][1] = As_hi[r1][tg];
            Ahi[mt][2] = As_hi[r0][tg + 4]; Ahi[mt][3] = As_hi[r1][tg + 4];
            Alo[mt][0] = As_lo[r0][tg];     Alo[mt][1] = As_lo[r1][tg];
            Alo[mt][2] = As_lo[r0][tg + 4]; Alo[mt][3] = As_lo[r1][tg + 4];
        }
#pragma unroll
        for (int nt = 0; nt < 4; nt++) {
            int c = wn * 32 + nt * 8 + g;
            Bhi[nt][0] = Bs_hi[c][tg]; Bhi[nt][1] = Bs_hi[c][tg + 4];
            Blo[nt][0] = Bs_lo[c][tg]; Blo[nt][1] = Bs_lo[c][tg + 4];
        }

#pragma unroll
        for (int mt = 0; mt < 2; mt++)
#pragma unroll
            for (int nt = 0; nt < 4; nt++) {
                mma_bf16(acc[mt][nt], Ahi[mt], Bhi[nt]);
                mma_bf16(acc[mt][nt], Alo[mt], Bhi[nt]);
                mma_bf16(acc[mt][nt], Ahi[mt], Blo[nt]);
            }
        __syncthreads();
    }

    // epilogue: scale by norm_src, convert to fp16, store
#pragma unroll
    for (int mt = 0; mt < 2; mt++) {
        int row0 = block_row + wm * 32 + mt * 16 + g;
        int row1 = row0 + 8;
        float ns0 = (row0 < N_NODES) ? g_norm_src[row0] : 0.f;
        float ns1 = (row1 < N_NODES) ? g_norm_src[row1] : 0.f;
#pragma unroll
        for (int nt = 0; nt < 4; nt++) {
            int col = wn * 32 + nt * 8 + 2 * tg;
            if (row0 < N_NODES) {
                __half2 v = __floats2half2_rn(acc[mt][nt][0] * ns0, acc[mt][nt][1] * ns0);
                *(__half2*)&g_xw[(size_t)row0 * HID + col] = v;
            }
            if (row1 < N_NODES) {
                __half2 v = __floats2half2_rn(acc[mt][nt][2] * ns1, acc[mt][nt][3] * ns1);
                *(__half2*)&g_xw[(size_t)row1 * HID + col] = v;
            }
        }
    }
}

// ---------------- prefix scan over in_cnt (3 phases) -------------------------
__global__ void __launch_bounds__(SCAN_BLK) scanA_kernel() {
    __shared__ int sh[SCAN_BLK];
    int tid = threadIdx.x;
    int i = blockIdx.x * SCAN_BLK + tid;
    int v = (i < N_NODES) ? g_in_cnt[i] : 0;
    sh[tid] = v;
    __syncthreads();
#pragma unroll
    for (int off = 1; off < SCAN_BLK; off <<= 1) {
        int t = (tid >= off) ? sh[tid - off] : 0;
        __syncthreads();
        sh[tid] += t;
        __syncthreads();
    }
    if (i < N_NODES) g_row_start[i] = sh[tid];
    if (tid == SCAN_BLK - 1) g_blk_sums[blockIdx.x] = sh[tid];
}

__global__ void scanB_kernel() {
    __shared__ int sh[128];
    int tid = threadIdx.x;
    int v = (tid < NUM_SCAN_BLKS) ? g_blk_sums[tid] : 0;
    sh[tid] = v;
    __syncthreads();
#pragma unroll
    for (int off = 1; off < 128; off <<= 1) {
        int t = (tid >= off) ? sh[tid - off] : 0;
        __syncthreads();
        sh[tid] += t;
        __syncthreads();
    }
    if (tid < NUM_SCAN_BLKS) g_blk_off[tid] = sh[tid] - v;
}

__global__ void scanC_kernel() {
    int i = blockIdx.x * blockDim.x + threadIdx.x;
    if (i >= N_NODES) return;
    int excl = g_row_start[i] - g_in_cnt[i] + g_blk_off[i >> 10];
    g_row_start[i] = excl;
    g_cursor[i] = excl;
}

// ---------------- scatter edges into CSR (grouped by dst) --------------------
__global__ void scatter_kernel(int E) {
    int e = blockIdx.x * blockDim.x + threadIdx.x;
    if (e >= E) return;
    int d = g_dst32[e];
    int pos = atomicAdd(&g_cursor[d], 1);
    g_csr_src[pos] = g_src32[e];
}

// ---------------- fused layer1: CSR segmented sum + relu + lin2 --------------
// warp per dst node; fp16 gather (8B per lane per message), fp32 accum.
__global__ void __launch_bounds__(256) agg1_fused_kernel(const float* __restrict__ b1,
                                                         const float* __restrict__ W2) {
    __shared__ float sW2[HID * 2];
    __shared__ float sb1[HID];
    for (int i = threadIdx.x; i < HID * 2; i += 256) sW2[i] = W2[i];
    for (int i = threadIdx.x; i < HID; i += 256) sb1[i] = b1[i];
    __syncthreads();

    int gid = blockIdx.x * blockDim.x + threadIdx.x;
    int row = gid >> 5;
    if (row >= N_NODES) return;
    int lane = gid & 31;

    int start = g_row_start[row];
    int cnt   = g_in_cnt[row];
    int end   = start + cnt;

    const __half* xw = g_xw;
    float4 acc = make_float4(0.f, 0.f, 0.f, 0.f);
    int e = start;
    for (; e + 3 < end; e += 4) {
        int s0 = __ldg(&g_csr_src[e + 0]);
        int s1 = __ldg(&g_csr_src[e + 1]);
        int s2 = __ldg(&g_csr_src[e + 2]);
        int s3 = __ldg(&g_csr_src[e + 3]);
        uint2 u0 = *(const uint2*)&xw[(size_t)s0 * HID + lane * 4];
        uint2 u1 = *(const uint2*)&xw[(size_t)s1 * HID + lane * 4];
        uint2 u2 = *(const uint2*)&xw[(size_t)s2 * HID + lane * 4];
        uint2 u3 = *(const uint2*)&xw[(size_t)s3 * HID + lane * 4];
        float2 a0 = __half22float2(*(__half2*)&u0.x), c0 = __half22float2(*(__half2*)&u0.y);
        float2 a1 = __half22float2(*(__half2*)&u1.x), c1 = __half22float2(*(__half2*)&u1.y);
        float2 a2 = __half22float2(*(__half2*)&u2.x), c2 = __half22float2(*(__half2*)&u2.y);
        float2 a3 = __half22float2(*(__half2*)&u3.x), c3 = __half22float2(*(__half2*)&u3.y);
        acc.x += (a0.x + a1.x) + (a2.x + a3.x);
        acc.y += (a0.y + a1.y) + (a2.y + a3.y);
        acc.z += (c0.x + c1.x) + (c2.x + c3.x);
        acc.w += (c0.y + c1.y) + (c2.y + c3.y);
    }
    for (; e < end; e++) {
        int s0 = __ldg(&g_csr_src[e]);
        uint2 u0 = *(const uint2*)&xw[(size_t)s0 * HID + lane * 4];
        float2 a0 = __half22float2(*(__half2*)&u0.x), c0 = __half22float2(*(__half2*)&u0.y);
        acc.x += a0.x; acc.y += a0.y; acc.z += c0.x; acc.w += c0.y;
    }

    float nd = g_norm_dst[row];
    int k0 = lane * 4;
    float h0 = fmaxf(acc.x * nd + sb1[k0 + 0], 0.f);
    float h1 = fmaxf(acc.y * nd + sb1[k0 + 1], 0.f);
    float h2 = fmaxf(acc.z * nd + sb1[k0 + 2], 0.f);
    float h3 = fmaxf(acc.w * nd + sb1[k0 + 3], 0.f);

    float s0 = h0 * sW2[(k0 + 0) * 2] + h1 * sW2[(k0 + 1) * 2]
             + h2 * sW2[(k0 + 2) * 2] + h3 * sW2[(k0 + 3) * 2];
    float s1 = h0 * sW2[(k0 + 0) * 2 + 1] + h1 * sW2[(k0 + 1) * 2 + 1]
             + h2 * sW2[(k0 + 2) * 2 + 1] + h3 * sW2[(k0 + 3) * 2 + 1];
#pragma unroll
    for (int off = 16; off > 0; off >>= 1) {
        s0 += __shfl_down_sync(0xffffffffu, s0, off);
        s1 += __shfl_down_sync(0xffffffffu, s1, off);
    }
    if (lane == 0) {
        float ns = g_norm_src[row];
        g_zs[row * 2 + 0] = s0 * ns;
        g_zs[row * 2 + 1] = s1 * ns;
    }
}

// ---------------- fused layer2: CSR segmented sum + softmax ------------------
__global__ void agg2_fused_kernel(const float* __restrict__ b2, float* __restrict__ out) {
    int i = blockIdx.x * blockDim.x + threadIdx.x;
    if (i >= N_NODES) return;
    int start = g_row_start[i];
    int end = start + g_in_cnt[i];
    float a0 = 0.f, a1 = 0.f;
    int e = start;
    for (; e + 1 < end; e += 2) {
        int s0 = __ldg(&g_csr_src[e]);
        int s1 = __ldg(&g_csr_src[e + 1]);
        float2 v0 = *(const float2*)&g_zs[s0 * 2];
        float2 v1 = *(const float2*)&g_zs[s1 * 2];
        a0 += v0.x + v1.x;
        a1 += v0.y + v1.y;
    }
    if (e < end) {
        int s = __ldg(&g_csr_src[e]);
        float2 v = *(const float2*)&g_zs[s * 2];
        a0 += v.x;
        a1 += v.y;
    }
    float nd = g_norm_dst[i];
    float z0 = a0 * nd + __ldg(&b2[0]);
    float z1 = a1 * nd + __ldg(&b2[1]);
    float m = fmaxf(z0, z1);
    float e0 = __expf(z0 - m);
    float e1 = __expf(z1 - m);
    float inv = 1.0f / (e0 + e1);
    out[i * 2 + 0] = e0 * inv;
    out[i * 2 + 1] = e1 * inv;
}

// ---------------- host ------------------------------------------------------
extern "C" void kernel_launch(void* const* d_in, const int* in_sizes, int n_in,
                              void* d_out, int out_size) {
    const float* X  = (const float*)d_in[0];
    const float* W1 = (const float*)d_in[1];
    const float* b1 = (const float*)d_in[2];
    const float* W2 = (const float*)d_in[3];
    const float* b2 = (const float*)d_in[4];
    const void*  sp = d_in[5];
    const void*  dp = d_in[6];
    const int E = in_sizes[5];
    float* out = (float*)d_out;

    // Launch order places gemm1 at position 4 so ncu (-s 5 -c 1) captures it.
    zerodetect_kernel<<<(N_NODES + 255) / 256, 256>>>(sp, E);          // 1
    convert_degree_kernel<<<(E + 255) / 256, 256>>>(sp, dp, E);        // 2
    norm_kernel<<<(N_NODES + 255) / 256, 256>>>();                     // 3
    gemm1_tc_kernel<<<(N_NODES + 127) / 128, 512>>>(X, W1);            // 4 <- profiled
    scanA_kernel<<<NUM_SCAN_BLKS, SCAN_BLK>>>();                       // 5
    scanB_kernel<<<1, 128>>>();                                        // 6
    scanC_kernel<<<(N_NODES + 255) / 256, 256>>>();                    // 7
    scatter_kernel<<<(E + 255) / 256, 256>>>(E);                       // 8
    {
        long long threads = (long long)N_NODES * 32;
        agg1_fused_kernel<<<(unsigned)((threads + 255) / 256), 256>>>(b1, W2);  // 9
    }
    agg2_fused_kernel<<<(N_NODES + 255) / 256, 256>>>(b2, out);        // 10
}

// round 13
// speedup vs baseline: 1.7368x; 1.1926x over previous
#include <cuda_runtime.h>
#include <cuda_bf16.h>
#include <cuda_fp16.h>
#include <cstdint>

#define N_NODES 100000
#define IN_F    512
#define HID     128
#define NCLS    2
#define MAX_E   1600000
#define SCAN_BLK 1024
#define NUM_SCAN_BLKS ((N_NODES + SCAN_BLK - 1) / SCAN_BLK)   // 98

// smem tile row stride in uint32 words: 48B rows -> 16B-aligned ldmatrix rows,
// and (3*row + chunk) mod 8 is a bijection -> conflict-free LDSM phases.
#define TPAD 12

// ---------------- device scratch (static globals; no runtime allocation) ----
__device__ __half g_xw [(size_t)N_NODES * HID];   // fp16: norm_src * (X@W1)
__device__ float  g_zs [(size_t)N_NODES * NCLS];  // norm_src * (h@W2)
__device__ float  g_norm_src[N_NODES];
__device__ float  g_norm_dst[N_NODES];
__device__ int    g_src32[MAX_E];
__device__ int    g_dst32[MAX_E];
__device__ int    g_csr_src[MAX_E];
__device__ int    g_in_cnt[N_NODES];
__device__ int    g_out_cnt[N_NODES];
__device__ int    g_row_start[N_NODES];
__device__ int    g_cursor[N_NODES];
__device__ int    g_blk_sums[NUM_SCAN_BLKS];
__device__ int    g_blk_off[NUM_SCAN_BLKS];
__device__ int    g_is64;

// ---------------- zero histograms + index dtype detection (fused) -----------
__global__ void zerodetect_kernel(const void* src_raw, int E) {
    int i = blockIdx.x * blockDim.x + threadIdx.x;
    if (i < N_NODES) {
        g_in_cnt[i] = 0;
        g_out_cnt[i] = 0;
    }
    if (blockIdx.x == 0 && threadIdx.x == 0) {
        const unsigned int* p = (const unsigned int*)src_raw;
        int n = E < 64 ? E : 64;
        int is64 = 1;
        for (int j = 0; j < n; j++)
            if (p[2 * j + 1] != 0u) is64 = 0;
        g_is64 = is64;
    }
}

// ---------------- convert + degree histograms -------------------------------
__global__ void convert_degree_kernel(const void* src_raw, const void* dst_raw, int E) {
    int i = blockIdx.x * blockDim.x + threadIdx.x;
    if (i >= E) return;
    int s, d;
    if (g_is64) {
        s = (int)((const long long*)src_raw)[i];
        d = (int)((const long long*)dst_raw)[i];
    } else {
        s = ((const int*)src_raw)[i];
        d = ((const int*)dst_raw)[i];
    }
    g_src32[i] = s;
    g_dst32[i] = d;
    atomicAdd(&g_out_cnt[s], 1);
    atomicAdd(&g_in_cnt[d], 1);
}

// ---------------- norms (before GEMM so epilogue can scale) ------------------
__global__ void norm_kernel() {
    int i = blockIdx.x * blockDim.x + threadIdx.x;
    if (i >= N_NODES) return;
    g_norm_src[i] = rsqrtf(fmaxf((float)g_out_cnt[i], 1.0f));
    g_norm_dst[i] = rsqrtf(fmaxf((float)g_in_cnt[i], 1.0f));
}

// ---------------- GEMM1 (mma.sync + ldmatrix; fp16 output) ------------------
__device__ __forceinline__ void mma_bf16(float* c, const uint32_t* a, const uint32_t* b) {
    asm volatile(
        "mma.sync.aligned.m16n8k16.row.col.f32.bf16.bf16.f32 "
        "{%0,%1,%2,%3}, {%4,%5,%6,%7}, {%8,%9}, {%0,%1,%2,%3};\n"
        : "+f"(c[0]), "+f"(c[1]), "+f"(c[2]), "+f"(c[3])
        : "r"(a[0]), "r"(a[1]), "r"(a[2]), "r"(a[3]), "r"(b[0]), "r"(b[1]));
}

__device__ __forceinline__ void ldsm_x4(uint32_t* r, uint32_t saddr) {
    asm volatile("ldmatrix.sync.aligned.m8n8.x4.shared.b16 {%0,%1,%2,%3}, [%4];"
                 : "=r"(r[0]), "=r"(r[1]), "=r"(r[2]), "=r"(r[3]) : "r"(saddr));
}

__device__ __forceinline__ uint32_t smem_u32(const void* p) {
    uint32_t a;
    asm("{ .reg .u64 t; cvta.to.shared.u64 t, %1; cvt.u32.u64 %0, t; }" : "=r"(a) : "l"(p));
    return a;
}

__device__ __forceinline__ uint32_t pack_bf16_hi(float x, float y,
                                                 float& lox, float& loy) {
    __nv_bfloat16 hx = __float2bfloat16(x);
    __nv_bfloat16 hy = __float2bfloat16(y);
    lox = x - __bfloat162float(hx);
    loy = y - __bfloat162float(hy);
    __nv_bfloat162 p = __halves2bfloat162(hx, hy);
    return *reinterpret_cast<uint32_t*>(&p);
}

__device__ __forceinline__ uint32_t pack_bf16(float x, float y) {
    __nv_bfloat162 p = __halves2bfloat162(__float2bfloat16(x), __float2bfloat16(y));
    return *reinterpret_cast<uint32_t*>(&p);
}

__global__ void __launch_bounds__(512, 1) gemm1_tc_kernel(const float* __restrict__ X,
                                                          const float* __restrict__ W1) {
    __shared__ uint32_t As_hi[128][TPAD];
    __shared__ uint32_t As_lo[128][TPAD];
    __shared__ uint32_t Bs_hi[128][TPAD];
    __shared__ uint32_t Bs_lo[128][TPAD];

    const int tid = threadIdx.x;
    const int warp = tid >> 5;
    const int lane = tid & 31;
    const int g  = lane >> 2;
    const int tg = lane & 3;
    const int wm = warp >> 2;
    const int wn = warp & 3;
    const int block_row = blockIdx.x * 128;

    int a_row[2], a_kp[2], b_n[2], b_kp[2];
#pragma unroll
    for (int it = 0; it < 2; it++) {
        int idx = tid + it * 512;
        a_row[it] = idx >> 3;
        a_kp[it]  = idx & 7;
        b_n[it]   = idx & 127;     // [k][n] fp32 W1, coalesced over n
        b_kp[it]  = idx >> 7;
    }

    // ldmatrix source addresses (loop-invariant); rows are 48B apart -> 16B aligned
    const int quad = lane >> 3;
    const int rrow = lane & 7;
    uint32_t a_off[2], b_off[2];
#pragma unroll
    for (int mt = 0; mt < 2; mt++) {
        int arow = wm * 32 + mt * 16 + ((quad & 1) ? 8 : 0) + rrow;
        int awrd = (quad & 2) ? 4 : 0;
        a_off[mt] = (uint32_t)((arow * TPAD + awrd) * 4);
    }
#pragma unroll
    for (int p = 0; p < 2; p++) {
        int brow = wn * 32 + p * 16 + ((quad & 2) ? 8 : 0) + rrow;
        int bwrd = (quad & 1) ? 4 : 0;
        b_off[p] = (uint32_t)((brow * TPAD + bwrd) * 4);
    }
    const uint32_t as_hi_b = smem_u32(As_hi);
    const uint32_t as_lo_b = smem_u32(As_lo);
    const uint32_t bs_hi_b = smem_u32(Bs_hi);
    const uint32_t bs_lo_b = smem_u32(Bs_lo);

    float acc[2][4][4];
#pragma unroll
    for (int mt = 0; mt < 2; mt++)
#pragma unroll
        for (int nt = 0; nt < 4; nt++)
#pragma unroll
            for (int r = 0; r < 4; r++) acc[mt][nt][r] = 0.f;

    float2 pa[2];
    float  pb0[2], pb1[2];

    auto load_tile = [&](int kk) {
#pragma unroll
        for (int it = 0; it < 2; it++) {
            int gr = block_row + a_row[it];
            float2 v = make_float2(0.f, 0.f);
            if (gr < N_NODES)
                v = *(const float2*)(X + (size_t)gr * IN_F + kk + a_kp[it] * 2);
            pa[it] = v;
            pb0[it] = W1[(size_t)(kk + 2 * b_kp[it]) * HID + b_n[it]];
            pb1[it] = W1[(size_t)(kk + 2 * b_kp[it] + 1) * HID + b_n[it]];
        }
    };

    auto store_tile = [&]() {
#pragma unroll
        for (int it = 0; it < 2; it++) {
            float lx, ly;
            As_hi[a_row[it]][a_kp[it]] = pack_bf16_hi(pa[it].x, pa[it].y, lx, ly);
            As_lo[a_row[it]][a_kp[it]] = pack_bf16(lx, ly);
            float blx, bly;
            Bs_hi[b_n[it]][b_kp[it]] = pack_bf16_hi(pb0[it], pb1[it], blx, bly);
            Bs_lo[b_n[it]][b_kp[it]] = pack_bf16(blx, bly);
        }
    };

    load_tile(0);

    for (int kk = 0; kk < IN_F; kk += 16) {
        store_tile();
        __syncthreads();

        if (kk + 16 < IN_F) load_tile(kk + 16);

        uint32_t Ahi[2][4], Alo[2][4], Bhi[2][4], Blo[2][4];
#pragma unroll
        for (int mt = 0; mt < 2; mt++) {
            ldsm_x4(Ahi[mt], as_hi_b + a_off[mt]);
            ldsm_x4(Alo[mt], as_lo_b + a_off[mt]);
        }
#pragma unroll
        for (int p = 0; p < 2; p++) {
            ldsm_x4(Bhi[p], bs_hi_b + b_off[p]);
            ldsm_x4(Blo[p], bs_lo_b + b_off[p]);
        }

#pragma unroll
        for (int mt = 0; mt < 2; mt++)
#pragma unroll
            for (int nt = 0; nt < 4; nt++) {
                const int p = nt >> 1;
                const int h = (nt & 1) * 2;
                mma_bf16(acc[mt][nt], Ahi[mt], &Bhi[p][h]);
                mma_bf16(acc[mt][nt], Alo[mt], &Bhi[p][h]);
                mma_bf16(acc[mt][nt], Ahi[mt], &Blo[p][h]);
            }
        __syncthreads();
    }

    // epilogue: scale by norm_src, convert to fp16, store
#pragma unroll
    for (int mt = 0; mt < 2; mt++) {
        int row0 = block_row + wm * 32 + mt * 16 + g;
        int row1 = row0 + 8;
        float ns0 = (row0 < N_NODES) ? g_norm_src[row0] : 0.f;
        float ns1 = (row1 < N_NODES) ? g_norm_src[row1] : 0.f;
#pragma unroll
        for (int nt = 0; nt < 4; nt++) {
            int col = wn * 32 + nt * 8 + 2 * tg;
            if (row0 < N_NODES) {
                __half2 v = __floats2half2_rn(acc[mt][nt][0] * ns0, acc[mt][nt][1] * ns0);
                *(__half2*)&g_xw[(size_t)row0 * HID + col] = v;
            }
            if (row1 < N_NODES) {
                __half2 v = __floats2half2_rn(acc[mt][nt][2] * ns1, acc[mt][nt][3] * ns1);
                *(__half2*)&g_xw[(size_t)row1 * HID + col] = v;
            }
        }
    }
}

// ---------------- prefix scan over in_cnt (3 phases) -------------------------
__global__ void __launch_bounds__(SCAN_BLK) scanA_kernel() {
    __shared__ int sh[SCAN_BLK];
    int tid = threadIdx.x;
    int i = blockIdx.x * SCAN_BLK + tid;
    int v = (i < N_NODES) ? g_in_cnt[i] : 0;
    sh[tid] = v;
    __syncthreads();
#pragma unroll
    for (int off = 1; off < SCAN_BLK; off <<= 1) {
        int t = (tid >= off) ? sh[tid - off] : 0;
        __syncthreads();
        sh[tid] += t;
        __syncthreads();
    }
    if (i < N_NODES) g_row_start[i] = sh[tid];
    if (tid == SCAN_BLK - 1) g_blk_sums[blockIdx.x] = sh[tid];
}

__global__ void scanB_kernel() {
    __shared__ int sh[128];
    int tid = threadIdx.x;
    int v = (tid < NUM_SCAN_BLKS) ? g_blk_sums[tid] : 0;
    sh[tid] = v;
    __syncthreads();
#pragma unroll
    for (int off = 1; off < 128; off <<= 1) {
        int t = (tid >= off) ? sh[tid - off] : 0;
        __syncthreads();
        sh[tid] += t;
        __syncthreads();
    }
    if (tid < NUM_SCAN_BLKS) g_blk_off[tid] = sh[tid] - v;
}

__global__ void scanC_kernel() {
    int i = blockIdx.x * blockDim.x + threadIdx.x;
    if (i >= N_NODES) return;
    int excl = g_row_start[i] - g_in_cnt[i] + g_blk_off[i >> 10];
    g_row_start[i] = excl;
    g_cursor[i] = excl;
}

// ---------------- scatter edges into CSR (grouped by dst) --------------------
__global__ void scatter_kernel(int E) {
    int e = blockIdx.x * blockDim.x + threadIdx.x;
    if (e >= E) return;
    int d = g_dst32[e];
    int pos = atomicAdd(&g_cursor[d], 1);
    g_csr_src[pos] = g_src32[e];
}

// ---------------- fused layer1: CSR segmented sum + relu + lin2 --------------
// warp per dst node; fp16 gather (8B per lane per message), fp32 accum.
__global__ void __launch_bounds__(256) agg1_fused_kernel(const float* __restrict__ b1,
                                                         const float* __restrict__ W2) {
    __shared__ float sW2[HID * 2];
    __shared__ float sb1[HID];
    for (int i = threadIdx.x; i < HID * 2; i += 256) sW2[i] = W2[i];
    for (int i = threadIdx.x; i < HID; i += 256) sb1[i] = b1[i];
    __syncthreads();

    int gid = blockIdx.x * blockDim.x + threadIdx.x;
    int row = gid >> 5;
    if (row >= N_NODES) return;
    int lane = gid & 31;

    int start = g_row_start[row];
    int cnt   = g_in_cnt[row];
    int end   = start + cnt;

    const __half* xw = g_xw;
    float4 acc = make_float4(0.f, 0.f, 0.f, 0.f);
    int e = start;
    for (; e + 3 < end; e += 4) {
        int s0 = __ldg(&g_csr_src[e + 0]);
        int s1 = __ldg(&g_csr_src[e + 1]);
        int s2 = __ldg(&g_csr_src[e + 2]);
        int s3 = __ldg(&g_csr_src[e + 3]);
        uint2 u0 = *(const uint2*)&xw[(size_t)s0 * HID + lane * 4];
        uint2 u1 = *(const uint2*)&xw[(size_t)s1 * HID + lane * 4];
        uint2 u2 = *(const uint2*)&xw[(size_t)s2 * HID + lane * 4];
        uint2 u3 = *(const uint2*)&xw[(size_t)s3 * HID + lane * 4];
        float2 a0 = __half22float2(*(__half2*)&u0.x), c0 = __half22float2(*(__half2*)&u0.y);
        float2 a1 = __half22float2(*(__half2*)&u1.x), c1 = __half22float2(*(__half2*)&u1.y);
        float2 a2 = __half22float2(*(__half2*)&u2.x), c2 = __half22float2(*(__half2*)&u2.y);
        float2 a3 = __half22float2(*(__half2*)&u3.x), c3 = __half22float2(*(__half2*)&u3.y);
        acc.x += (a0.x + a1.x) + (a2.x + a3.x);
        acc.y += (a0.y + a1.y) + (a2.y + a3.y);
        acc.z += (c0.x + c1.x) + (c2.x + c3.x);
        acc.w += (c0.y + c1.y) + (c2.y + c3.y);
    }
    for (; e < end; e++) {
        int s0 = __ldg(&g_csr_src[e]);
        uint2 u0 = *(const uint2*)&xw[(size_t)s0 * HID + lane * 4];
        float2 a0 = __half22float2(*(__half2*)&u0.x), c0 = __half22float2(*(__half2*)&u0.y);
        acc.x += a0.x; acc.y += a0.y; acc.z += c0.x; acc.w += c0.y;
    }

    float nd = g_norm_dst[row];
    int k0 = lane * 4;
    float h0 = fmaxf(acc.x * nd + sb1[k0 + 0], 0.f);
    float h1 = fmaxf(acc.y * nd + sb1[k0 + 1], 0.f);
    float h2 = fmaxf(acc.z * nd + sb1[k0 + 2], 0.f);
    float h3 = fmaxf(acc.w * nd + sb1[k0 + 3], 0.f);

    float s0 = h0 * sW2[(k0 + 0) * 2] + h1 * sW2[(k0 + 1) * 2]
             + h2 * sW2[(k0 + 2) * 2] + h3 * sW2[(k0 + 3) * 2];
    float s1 = h0 * sW2[(k0 + 0) * 2 + 1] + h1 * sW2[(k0 + 1) * 2 + 1]
             + h2 * sW2[(k0 + 2) * 2 + 1] + h3 * sW2[(k0 + 3) * 2 + 1];
#pragma unroll
    for (int off = 16; off > 0; off >>= 1) {
        s0 += __shfl_down_sync(0xffffffffu, s0, off);
        s1 += __shfl_down_sync(0xffffffffu, s1, off);
    }
    if (lane == 0) {
        float ns = g_norm_src[row];
        g_zs[row * 2 + 0] = s0 * ns;
        g_zs[row * 2 + 1] = s1 * ns;
    }
}

// ---------------- fused layer2: CSR segmented sum + softmax ------------------
__global__ void agg2_fused_kernel(const float* __restrict__ b2, float* __restrict__ out) {
    int i = blockIdx.x * blockDim.x + threadIdx.x;
    if (i >= N_NODES) return;
    int start = g_row_start[i];
    int end = start + g_in_cnt[i];
    float a0 = 0.f, a1 = 0.f;
    int e = start;
    for (; e + 1 < end; e += 2) {
        int s0 = __ldg(&g_csr_src[e]);
        int s1 = __ldg(&g_csr_src[e + 1]);
        float2 v0 = *(const float2*)&g_zs[s0 * 2];
        float2 v1 = *(const float2*)&g_zs[s1 * 2];
        a0 += v0.x + v1.x;
        a1 += v0.y + v1.y;
    }
    if (e < end) {
        int s = __ldg(&g_csr_src[e]);
        float2 v = *(const float2*)&g_zs[s * 2];
        a0 += v.x;
        a1 += v.y;
    }
    float nd = g_norm_dst[i];
    float z0 = a0 * nd + __ldg(&b2[0]);
    float z1 = a1 * nd + __ldg(&b2[1]);
    float m = fmaxf(z0, z1);
    float e0 = __expf(z0 - m);
    float e1 = __expf(z1 - m);
    float inv = 1.0f / (e0 + e1);
    out[i * 2 + 0] = e0 * inv;
    out[i * 2 + 1] = e1 * inv;
}

// ---------------- host ------------------------------------------------------
extern "C" void kernel_launch(void* const* d_in, const int* in_sizes, int n_in,
                              void* d_out, int out_size) {
    const float* X  = (const float*)d_in[0];
    const float* W1 = (const float*)d_in[1];
    const float* b1 = (const float*)d_in[2];
    const float* W2 = (const float*)d_in[3];
    const float* b2 = (const float*)d_in[4];
    const void*  sp = d_in[5];
    const void*  dp = d_in[6];
    const int E = in_sizes[5];
    float* out = (float*)d_out;

    // gemm1 is launch #4 so ncu (-s 5 -c 1) captures it.
    zerodetect_kernel<<<(N_NODES + 255) / 256, 256>>>(sp, E);          // 1
    convert_degree_kernel<<<(E + 255) / 256, 256>>>(sp, dp, E);        // 2
    norm_kernel<<<(N_NODES + 255) / 256, 256>>>();                     // 3
    gemm1_tc_kernel<<<(N_NODES + 127) / 128, 512>>>(X, W1);            // 4 <- profiled
    scanA_kernel<<<NUM_SCAN_BLKS, SCAN_BLK>>>();                       // 5
    scanB_kernel<<<1, 128>>>();                                        // 6
    scanC_kernel<<<(N_NODES + 255) / 256, 256>>>();                    // 7
    scatter_kernel<<<(E + 255) / 256, 256>>>(E);                       // 8
    {
        long long threads = (long long)N_NODES * 32;
        agg1_fused_kernel<<<(unsigned)((threads + 255) / 256), 256>>>(b1, W2);  // 9
    }
    agg2_fused_kernel<<<(N_NODES + 255) / 256, 256>>>(b2, out);        // 10
}

// round 15
// speedup vs baseline: 1.7850x; 1.0277x over previous
#include <cuda_runtime.h>
#include <cuda_bf16.h>
#include <cuda_fp16.h>
#include <cstdint>

#define N_NODES 100000
#define IN_F    512
#define HID     128
#define NCLS    2
#define MAX_E   1600000
#define SCAN_BLK 1024
#define NUM_SCAN_BLKS ((N_NODES + SCAN_BLK - 1) / SCAN_BLK)   // 98

// smem tile row stride in uint32 words: 48B rows -> 16B-aligned ldmatrix rows,
// and (3*row + chunk) mod 8 is a bijection -> conflict-free LDSM phases.
#define TPAD 12

// GEMM CTA: 256 threads, 64 rows x 128 cols, 2 CTAs/SM for latency hiding.
#define GROWS 64

// ---------------- device scratch (static globals; no runtime allocation) ----
__device__ __half g_xw [(size_t)N_NODES * HID];   // fp16: norm_src * (X@W1)
__device__ float  g_zs [(size_t)N_NODES * NCLS];  // norm_src * (h@W2)
__device__ float  g_norm_src[N_NODES];
__device__ float  g_norm_dst[N_NODES];
__device__ int    g_src32[MAX_E];
__device__ int    g_dst32[MAX_E];
__device__ int    g_csr_src[MAX_E];
__device__ int    g_in_cnt[N_NODES];
__device__ int    g_out_cnt[N_NODES];
__device__ int    g_row_start[N_NODES];
__device__ int    g_cursor[N_NODES];
__device__ int    g_blk_sums[NUM_SCAN_BLKS];
__device__ int    g_blk_off[NUM_SCAN_BLKS];
__device__ int    g_is64;

// ---------------- zero histograms + index dtype detection (fused) -----------
__global__ void zerodetect_kernel(const void* src_raw, int E) {
    int i = blockIdx.x * blockDim.x + threadIdx.x;
    if (i < N_NODES) {
        g_in_cnt[i] = 0;
        g_out_cnt[i] = 0;
    }
    if (blockIdx.x == 0 && threadIdx.x == 0) {
        const unsigned int* p = (const unsigned int*)src_raw;
        int n = E < 64 ? E : 64;
        int is64 = 1;
        for (int j = 0; j < n; j++)
            if (p[2 * j + 1] != 0u) is64 = 0;
        g_is64 = is64;
    }
}

// ---------------- convert + degree histograms -------------------------------
__global__ void convert_degree_kernel(const void* src_raw, const void* dst_raw, int E) {
    int i = blockIdx.x * blockDim.x + threadIdx.x;
    if (i >= E) return;
    int s, d;
    if (g_is64) {
        s = (int)((const long long*)src_raw)[i];
        d = (int)((const long long*)dst_raw)[i];
    } else {
        s = ((const int*)src_raw)[i];
        d = ((const int*)dst_raw)[i];
    }
    g_src32[i] = s;
    g_dst32[i] = d;
    atomicAdd(&g_out_cnt[s], 1);
    atomicAdd(&g_in_cnt[d], 1);
}

// ---------------- norms (before GEMM so epilogue can scale) ------------------
__global__ void norm_kernel() {
    int i = blockIdx.x * blockDim.x + threadIdx.x;
    if (i >= N_NODES) return;
    g_norm_src[i] = rsqrtf(fmaxf((float)g_out_cnt[i], 1.0f));
    g_norm_dst[i] = rsqrtf(fmaxf((float)g_in_cnt[i], 1.0f));
}

// ---------------- GEMM1 (mma.sync + ldmatrix; fp16 output) ------------------
__device__ __forceinline__ void mma_bf16(float* c, const uint32_t* a, const uint32_t* b) {
    asm volatile(
        "mma.sync.aligned.m16n8k16.row.col.f32.bf16.bf16.f32 "
        "{%0,%1,%2,%3}, {%4,%5,%6,%7}, {%8,%9}, {%0,%1,%2,%3};\n"
        : "+f"(c[0]), "+f"(c[1]), "+f"(c[2]), "+f"(c[3])
        : "r"(a[0]), "r"(a[1]), "r"(a[2]), "r"(a[3]), "r"(b[0]), "r"(b[1]));
}

__device__ __forceinline__ void ldsm_x4(uint32_t* r, uint32_t saddr) {
    asm volatile("ldmatrix.sync.aligned.m8n8.x4.shared.b16 {%0,%1,%2,%3}, [%4];"
                 : "=r"(r[0]), "=r"(r[1]), "=r"(r[2]), "=r"(r[3]) : "r"(saddr));
}

__device__ __forceinline__ uint32_t smem_u32(const void* p) {
    uint32_t a;
    asm("{ .reg .u64 t; cvta.to.shared.u64 t, %1; cvt.u32.u64 %0, t; }" : "=r"(a) : "l"(p));
    return a;
}

__device__ __forceinline__ uint32_t pack_bf16_hi(float x, float y,
                                                 float& lox, float& loy) {
    __nv_bfloat16 hx = __float2bfloat16(x);
    __nv_bfloat16 hy = __float2bfloat16(y);
    lox = x - __bfloat162float(hx);
    loy = y - __bfloat162float(hy);
    __nv_bfloat162 p = __halves2bfloat162(hx, hy);
    return *reinterpret_cast<uint32_t*>(&p);
}

__device__ __forceinline__ uint32_t pack_bf16(float x, float y) {
    __nv_bfloat162 p = __halves2bfloat162(__float2bfloat16(x), __float2bfloat16(y));
    return *reinterpret_cast<uint32_t*>(&p);
}

__global__ void __launch_bounds__(256, 2) gemm1_tc_kernel(const float* __restrict__ X,
                                                          const float* __restrict__ W1) {
    __shared__ uint32_t As_hi[GROWS][TPAD];
    __shared__ uint32_t As_lo[GROWS][TPAD];
    __shared__ uint32_t Bs_hi[128][TPAD];
    __shared__ uint32_t Bs_lo[128][TPAD];

    const int tid = threadIdx.x;
    const int warp = tid >> 5;       // 0..7
    const int lane = tid & 31;
    const int g  = lane >> 2;
    const int tg = lane & 3;
    const int wm = warp >> 2;        // 0..1 -> 32-row slab
    const int wn = warp & 3;         // 0..3 -> 32-col slab
    const int block_row = blockIdx.x * GROWS;

    // loader coords: A: 2 units of 64x8; B: 4 units of 8x128 (fp32 pairs)
    int a_row[2], a_kp[2], b_n[4], b_kp[4];
#pragma unroll
    for (int it = 0; it < 2; it++) {
        int idx = tid + it * 256;     // 0..511
        a_row[it] = idx >> 3;         // 0..63
        a_kp[it]  = idx & 7;
    }
#pragma unroll
    for (int it = 0; it < 4; it++) {
        int idx = tid + it * 256;     // 0..1023
        b_n[it]  = idx & 127;         // coalesced over n
        b_kp[it] = idx >> 7;          // 0..7
    }

    // ldmatrix source addresses (loop-invariant); rows are 48B apart -> 16B aligned
    const int quad = lane >> 3;
    const int rrow = lane & 7;
    uint32_t a_off[2], b_off[2];
#pragma unroll
    for (int mt = 0; mt < 2; mt++) {
        int arow = wm * 32 + mt * 16 + ((quad & 1) ? 8 : 0) + rrow;
        int awrd = (quad & 2) ? 4 : 0;
        a_off[mt] = (uint32_t)((arow * TPAD + awrd) * 4);
    }
#pragma unroll
    for (int p = 0; p < 2; p++) {
        int brow = wn * 32 + p * 16 + ((quad & 2) ? 8 : 0) + rrow;
        int bwrd = (quad & 1) ? 4 : 0;
        b_off[p] = (uint32_t)((brow * TPAD + bwrd) * 4);
    }
    const uint32_t as_hi_b = smem_u32(As_hi);
    const uint32_t as_lo_b = smem_u32(As_lo);
    const uint32_t bs_hi_b = smem_u32(Bs_hi);
    const uint32_t bs_lo_b = smem_u32(Bs_lo);

    float acc[2][4][4];
#pragma unroll
    for (int mt = 0; mt < 2; mt++)
#pragma unroll
        for (int nt = 0; nt < 4; nt++)
#pragma unroll
            for (int r = 0; r < 4; r++) acc[mt][nt][r] = 0.f;

    float2 pa[2];
    float  pb0[4], pb1[4];

    auto load_tile = [&](int kk) {
#pragma unroll
        for (int it = 0; it < 2; it++) {
            int gr = block_row + a_row[it];
            float2 v = make_float2(0.f, 0.f);
            if (gr < N_NODES)
                v = *(const float2*)(X + (size_t)gr * IN_F + kk + a_kp[it] * 2);
            pa[it] = v;
        }
#pragma unroll
        for (int it = 0; it < 4; it++) {
            pb0[it] = W1[(size_t)(kk + 2 * b_kp[it]) * HID + b_n[it]];
            pb1[it] = W1[(size_t)(kk + 2 * b_kp[it] + 1) * HID + b_n[it]];
        }
    };

    auto store_tile = [&]() {
#pragma unroll
        for (int it = 0; it < 2; it++) {
            float lx, ly;
            As_hi[a_row[it]][a_kp[it]] = pack_bf16_hi(pa[it].x, pa[it].y, lx, ly);
            As_lo[a_row[it]][a_kp[it]] = pack_bf16(lx, ly);
        }
#pragma unroll
        for (int it = 0; it < 4; it++) {
            float blx, bly;
            Bs_hi[b_n[it]][b_kp[it]] = pack_bf16_hi(pb0[it], pb1[it], blx, bly);
            Bs_lo[b_n[it]][b_kp[it]] = pack_bf16(blx, bly);
        }
    };

    load_tile(0);

    for (int kk = 0; kk < IN_F; kk += 16) {
        store_tile();
        __syncthreads();

        if (kk + 16 < IN_F) load_tile(kk + 16);

        uint32_t Ahi[2][4], Alo[2][4], Bhi[2][4], Blo[2][4];
#pragma unroll
        for (int mt = 0; mt < 2; mt++) {
            ldsm_x4(Ahi[mt], as_hi_b + a_off[mt]);
            ldsm_x4(Alo[mt], as_lo_b + a_off[mt]);
        }
#pragma unroll
        for (int p = 0; p < 2; p++) {
            ldsm_x4(Bhi[p], bs_hi_b + b_off[p]);
            ldsm_x4(Blo[p], bs_lo_b + b_off[p]);
        }

#pragma unroll
        for (int mt = 0; mt < 2; mt++)
#pragma unroll
            for (int nt = 0; nt < 4; nt++) {
                const int p = nt >> 1;
                const int h = (nt & 1) * 2;
                mma_bf16(acc[mt][nt], Ahi[mt], &Bhi[p][h]);
                mma_bf16(acc[mt][nt], Alo[mt], &Bhi[p][h]);
                mma_bf16(acc[mt][nt], Ahi[mt], &Blo[p][h]);
            }
        __syncthreads();
    }

    // epilogue: scale by norm_src, convert to fp16, store
#pragma unroll
    for (int mt = 0; mt < 2; mt++) {
        int row0 = block_row + wm * 32 + mt * 16 + g;
        int row1 = row0 + 8;
        float ns0 = (row0 < N_NODES) ? g_norm_src[row0] : 0.f;
        float ns1 = (row1 < N_NODES) ? g_norm_src[row1] : 0.f;
#pragma unroll
        for (int nt = 0; nt < 4; nt++) {
            int col = wn * 32 + nt * 8 + 2 * tg;
            if (row0 < N_NODES) {
                __half2 v = __floats2half2_rn(acc[mt][nt][0] * ns0, acc[mt][nt][1] * ns0);
                *(__half2*)&g_xw[(size_t)row0 * HID + col] = v;
            }
            if (row1 < N_NODES) {
                __half2 v = __floats2half2_rn(acc[mt][nt][2] * ns1, acc[mt][nt][3] * ns1);
                *(__half2*)&g_xw[(size_t)row1 * HID + col] = v;
            }
        }
    }
}

// ---------------- prefix scan over in_cnt (3 phases) -------------------------
__global__ void __launch_bounds__(SCAN_BLK) scanA_kernel() {
    __shared__ int sh[SCAN_BLK];
    int tid = threadIdx.x;
    int i = blockIdx.x * SCAN_BLK + tid;
    int v = (i < N_NODES) ? g_in_cnt[i] : 0;
    sh[tid] = v;
    __syncthreads();
#pragma unroll
    for (int off = 1; off < SCAN_BLK; off <<= 1) {
        int t = (tid >= off) ? sh[tid - off] : 0;
        __syncthreads();
        sh[tid] += t;
        __syncthreads();
    }
    if (i < N_NODES) g_row_start[i] = sh[tid];
    if (tid == SCAN_BLK - 1) g_blk_sums[blockIdx.x] = sh[tid];
}

__global__ void scanB_kernel() {
    __shared__ int sh[128];
    int tid = threadIdx.x;
    int v = (tid < NUM_SCAN_BLKS) ? g_blk_sums[tid] : 0;
    sh[tid] = v;
    __syncthreads();
#pragma unroll
    for (int off = 1; off < 128; off <<= 1) {
        int t = (tid >= off) ? sh[tid - off] : 0;
        __syncthreads();
        sh[tid] += t;
        __syncthreads();
    }
    if (tid < NUM_SCAN_BLKS) g_blk_off[tid] = sh[tid] - v;
}

__global__ void scanC_kernel() {
    int i = blockIdx.x * blockDim.x + threadIdx.x;
    if (i >= N_NODES) return;
    int excl = g_row_start[i] - g_in_cnt[i] + g_blk_off[i >> 10];
    g_row_start[i] = excl;
    g_cursor[i] = excl;
}

// ---------------- scatter edges into CSR (grouped by dst) --------------------
__global__ void scatter_kernel(int E) {
    int e = blockIdx.x * blockDim.x + threadIdx.x;
    if (e >= E) return;
    int d = g_dst32[e];
    int pos = atomicAdd(&g_cursor[d], 1);
    g_csr_src[pos] = g_src32[e];
}

// ---------------- fused layer1: CSR segmented sum + relu + lin2 --------------
// warp per dst node; fp16 gather (8B per lane per message), fp32 accum.
__global__ void __launch_bounds__(256) agg1_fused_kernel(const float* __restrict__ b1,
                                                         const float* __restrict__ W2) {
    __shared__ float sW2[HID * 2];
    __shared__ float sb1[HID];
    for (int i = threadIdx.x; i < HID * 2; i += 256) sW2[i] = W2[i];
    for (int i = threadIdx.x; i < HID; i += 256) sb1[i] = b1[i];
    __syncthreads();

    int gid = blockIdx.x * blockDim.x + threadIdx.x;
    int row = gid >> 5;
    if (row >= N_NODES) return;
    int lane = gid & 31;

    int start = g_row_start[row];
    int cnt   = g_in_cnt[row];
    int end   = start + cnt;

    const __half* xw = g_xw;
    float4 acc = make_float4(0.f, 0.f, 0.f, 0.f);
    int e = start;
    for (; e + 3 < end; e += 4) {
        int s0 = __ldg(&g_csr_src[e + 0]);
        int s1 = __ldg(&g_csr_src[e + 1]);
        int s2 = __ldg(&g_csr_src[e + 2]);
        int s3 = __ldg(&g_csr_src[e + 3]);
        uint2 u0 = *(const uint2*)&xw[(size_t)s0 * HID + lane * 4];
        uint2 u1 = *(const uint2*)&xw[(size_t)s1 * HID + lane * 4];
        uint2 u2 = *(const uint2*)&xw[(size_t)s2 * HID + lane * 4];
        uint2 u3 = *(const uint2*)&xw[(size_t)s3 * HID + lane * 4];
        float2 a0 = __half22float2(*(__half2*)&u0.x), c0 = __half22float2(*(__half2*)&u0.y);
        float2 a1 = __half22float2(*(__half2*)&u1.x), c1 = __half22float2(*(__half2*)&u1.y);
        float2 a2 = __half22float2(*(__half2*)&u2.x), c2 = __half22float2(*(__half2*)&u2.y);
        float2 a3 = __half22float2(*(__half2*)&u3.x), c3 = __half22float2(*(__half2*)&u3.y);
        acc.x += (a0.x + a1.x) + (a2.x + a3.x);
        acc.y += (a0.y + a1.y) + (a2.y + a3.y);
        acc.z += (c0.x + c1.x) + (c2.x + c3.x);
        acc.w += (c0.y + c1.y) + (c2.y + c3.y);
    }
    for (; e < end; e++) {
        int s0 = __ldg(&g_csr_src[e]);
        uint2 u0 = *(const uint2*)&xw[(size_t)s0 * HID + lane * 4];
        float2 a0 = __half22float2(*(__half2*)&u0.x), c0 = __half22float2(*(__half2*)&u0.y);
        acc.x += a0.x; acc.y += a0.y; acc.z += c0.x; acc.w += c0.y;
    }

    float nd = g_norm_dst[row];
    int k0 = lane * 4;
    float h0 = fmaxf(acc.x * nd + sb1[k0 + 0], 0.f);
    float h1 = fmaxf(acc.y * nd + sb1[k0 + 1], 0.f);
    float h2 = fmaxf(acc.z * nd + sb1[k0 + 2], 0.f);
    float h3 = fmaxf(acc.w * nd + sb1[k0 + 3], 0.f);

    float s0 = h0 * sW2[(k0 + 0) * 2] + h1 * sW2[(k0 + 1) * 2]
             + h2 * sW2[(k0 + 2) * 2] + h3 * sW2[(k0 + 3) * 2];
    float s1 = h0 * sW2[(k0 + 0) * 2 + 1] + h1 * sW2[(k0 + 1) * 2 + 1]
             + h2 * sW2[(k0 + 2) * 2 + 1] + h3 * sW2[(k0 + 3) * 2 + 1];
#pragma unroll
    for (int off = 16; off > 0; off >>= 1) {
        s0 += __shfl_down_sync(0xffffffffu, s0, off);
        s1 += __shfl_down_sync(0xffffffffu, s1, off);
    }
    if (lane == 0) {
        float ns = g_norm_src[row];
        g_zs[row * 2 + 0] = s0 * ns;
        g_zs[row * 2 + 1] = s1 * ns;
    }
}

// ---------------- fused layer2: CSR segmented sum + softmax ------------------
__global__ void agg2_fused_kernel(const float* __restrict__ b2, float* __restrict__ out) {
    int i = blockIdx.x * blockDim.x + threadIdx.x;
    if (i >= N_NODES) return;
    int start = g_row_start[i];
    int end = start + g_in_cnt[i];
    float a0 = 0.f, a1 = 0.f;
    int e = start;
    for (; e + 1 < end; e += 2) {
        int s0 = __ldg(&g_csr_src[e]);
        int s1 = __ldg(&g_csr_src[e + 1]);
        float2 v0 = *(const float2*)&g_zs[s0 * 2];
        float2 v1 = *(const float2*)&g_zs[s1 * 2];
        a0 += v0.x + v1.x;
        a1 += v0.y + v1.y;
    }
    if (e < end) {
        int s = __ldg(&g_csr_src[e]);
        float2 v = *(const float2*)&g_zs[s * 2];
        a0 += v.x;
        a1 += v.y;
    }
    float nd = g_norm_dst[i];
    float z0 = a0 * nd + __ldg(&b2[0]);
    float z1 = a1 * nd + __ldg(&b2[1]);
    float m = fmaxf(z0, z1);
    float e0 = __expf(z0 - m);
    float e1 = __expf(z1 - m);
    float inv = 1.0f / (e0 + e1);
    out[i * 2 + 0] = e0 * inv;
    out[i * 2 + 1] = e1 * inv;
}

// ---------------- host ------------------------------------------------------
extern "C" void kernel_launch(void* const* d_in, const int* in_sizes, int n_in,
                              void* d_out, int out_size) {
    const float* X  = (const float*)d_in[0];
    const float* W1 = (const float*)d_in[1];
    const float* b1 = (const float*)d_in[2];
    const float* W2 = (const float*)d_in[3];
    const float* b2 = (const float*)d_in[4];
    const void*  sp = d_in[5];
    const void*  dp = d_in[6];
    const int E = in_sizes[5];
    float* out = (float*)d_out;

    // gemm1 is launch #4 so ncu (-s 5 -c 1) captures it.
    zerodetect_kernel<<<(N_NODES + 255) / 256, 256>>>(sp, E);          // 1
    convert_degree_kernel<<<(E + 255) / 256, 256>>>(sp, dp, E);        // 2
    norm_kernel<<<(N_NODES + 255) / 256, 256>>>();                     // 3
    gemm1_tc_kernel<<<(N_NODES + GROWS - 1) / GROWS, 256>>>(X, W1);    // 4 <- profiled
    scanA_kernel<<<NUM_SCAN_BLKS, SCAN_BLK>>>();                       // 5
    scanB_kernel<<<1, 128>>>();                                        // 6
    scanC_kernel<<<(N_NODES + 255) / 256, 256>>>();                    // 7
    scatter_kernel<<<(E + 255) / 256, 256>>>(E);                       // 8
    {
        long long threads = (long long)N_NODES * 32;
        agg1_fused_kernel<<<(unsigned)((threads + 255) / 256), 256>>>(b1, W2);  // 9
    }
    agg2_fused_kernel<<<(N_NODES + 255) / 256, 256>>>(b2, out);        // 10
}